// round 15
// baseline (speedup 1.0000x reference)
#include <cuda_runtime.h>
#include <cuda_fp16.h>

#define BB 8
#define HH 512
#define WW 512
#define HW (HH * WW)

#define TX 32
#define TYW 8                  // 256 threads
#define PY 8
#define TILE_H (TYW * PY)      // 64
#define SW 38                  // logical halo cols
#define SH (TILE_H + 6)        // 70
#define PITCH 40               // storage cols per row (si = 0..39)
#define CPY 2848               // halves per copy; copyB bank-shifted 64B vs copyA
#define NBLOCKS ((WW / TX) * (HH / TILE_H) * BB)   // 1024
#define NQUAD (SH * 10)        // 700 quad-elements (fast path)

__device__ unsigned long long g_pack = 0ULL;

__device__ __forceinline__ unsigned gt2(unsigned a, unsigned b) {
    return __hgt2_mask(*(const __half2*)&a, *(const __half2*)&b);
}

__global__ __launch_bounds__(TX * TYW, 6)
void census_fused(const float* __restrict__ pred, const float* __restrict__ tgt,
                  float* __restrict__ out) {
    // predA @0, predB @CPY (copyB[i] = elem si i+1), tgtA @2*CPY, tgtB @3*CPY
    __shared__ __align__(16) unsigned short sm[4 * CPY];
    __shared__ int wsum[TYW];

    const int b  = blockIdx.z;
    const int x0 = blockIdx.x * TX;
    const int y0 = blockIdx.y * TILE_H;
    const int tid = threadIdx.y * TX + threadIdx.x;

    const float* __restrict__ pb = pred + (size_t)b * 3 * HW;
    const float* __restrict__ tb = tgt  + (size_t)b * 3 * HW;

    const bool interiorBlk = (blockIdx.x > 0 && blockIdx.x + 1 < gridDim.x &&
                              blockIdx.y > 0 && blockIdx.y + 1 < gridDim.y);

    if (interiorBlk) {
        // -------- fast halo: float4 quad loads, no reflect, fixed 3 iters --------
        const int ax0 = x0 - 4;             // 16B-aligned quad start
#pragma unroll
        for (int it = 0; it < 3; it++) {
            int q = tid + it * (TX * TYW);
            if (q < NQUAD) {
                int ly = q / 10;
                int p  = q - ly * 10;       // quad index 0..9
                int off = (y0 + ly - 3) * WW + ax0 + 4 * p;
                float4 pr = *(const float4*)(pb + off);
                float4 pg = *(const float4*)(pb + HW + off);
                float4 pc = *(const float4*)(pb + 2 * HW + off);
                float4 tr = *(const float4*)(tb + off);
                float4 tg = *(const float4*)(tb + HW + off);
                float4 tc = *(const float4*)(tb + 2 * HW + off);
                __half2 hp01 = __floats2half2_rn(
                    fmaf(0.299f, pr.x, fmaf(0.587f, pg.x, 0.114f * pc.x)),
                    fmaf(0.299f, pr.y, fmaf(0.587f, pg.y, 0.114f * pc.y)));
                __half2 hp23 = __floats2half2_rn(
                    fmaf(0.299f, pr.z, fmaf(0.587f, pg.z, 0.114f * pc.z)),
                    fmaf(0.299f, pr.w, fmaf(0.587f, pg.w, 0.114f * pc.w)));
                __half2 ht01 = __floats2half2_rn(
                    fmaf(0.299f, tr.x, fmaf(0.587f, tg.x, 0.114f * tc.x)),
                    fmaf(0.299f, tr.y, fmaf(0.587f, tg.y, 0.114f * tc.y)));
                __half2 ht23 = __floats2half2_rn(
                    fmaf(0.299f, tr.z, fmaf(0.587f, tg.z, 0.114f * tc.z)),
                    fmaf(0.299f, tr.w, fmaf(0.587f, tg.w, 0.114f * tc.w)));
                unsigned p01 = *(unsigned*)&hp01, p23 = *(unsigned*)&hp23;
                unsigned t01 = *(unsigned*)&ht01, t23 = *(unsigned*)&ht23;
                int e = ly * PITCH + 4 * p;           // si of quad lo elem (4-aligned)
                // copyA: 4 halves = uint2 (STS.64)
                *(uint2*)&sm[e]           = make_uint2(p01, p23);
                *(uint2*)&sm[2 * CPY + e] = make_uint2(t01, t23);
                // copyB[i] = elem i+1: [e-1]=e0 (q>0), u32@[e]=(e1,e2), [e+2]=e3
                if (p > 0) {
                    sm[CPY + e - 1]     = (unsigned short)(p01 & 0xFFFFu);
                    sm[3 * CPY + e - 1] = (unsigned short)(t01 & 0xFFFFu);
                }
                *(unsigned*)&sm[CPY + e]     = __funnelshift_r(p01, p23, 16);
                *(unsigned*)&sm[3 * CPY + e] = __funnelshift_r(t01, t23, 16);
                sm[CPY + e + 2]     = (unsigned short)(p23 >> 16);
                sm[3 * CPY + e + 2] = (unsigned short)(t23 >> 16);
            }
        }
    } else {
        // -------- border halo: scalar loads with reflect padding --------
        for (int idx = tid; idx < SH * SW; idx += TX * TYW) {
            int ly = idx / SW;
            int lx = idx - ly * SW;
            int gy = y0 + ly - 3;
            gy = (gy < 0) ? -gy : ((gy >= HH) ? 2 * HH - 2 - gy : gy);
            int gx = x0 + lx - 3;
            gx = (gx < 0) ? -gx : ((gx >= WW) ? 2 * WW - 2 - gx : gx);
            int off = gy * WW + gx;
            float gp = fmaf(0.299f, pb[off], fmaf(0.587f, pb[HW + off], 0.114f * pb[2 * HW + off]));
            float gt = fmaf(0.299f, tb[off], fmaf(0.587f, tb[HW + off], 0.114f * tb[2 * HW + off]));
            unsigned short hp = __half_as_ushort(__float2half_rn(gp));
            unsigned short ht = __half_as_ushort(__float2half_rn(gt));
            int si = lx + 1;                 // storage index (0 and 39 unused/unread)
            int ib = ly * PITCH + si;
            sm[ib] = hp;
            sm[2 * CPY + ib] = ht;
            sm[CPY + ib - 1] = hp;           // copyB[si-1] = elem si
            sm[3 * CPY + ib - 1] = ht;
        }
    }
    __syncthreads();

    // -------- census core (window col j <-> si = tx+1+j) --------
    const int tx   = threadIdx.x;
    const int base = threadIdx.y * PY;
    const int s    = tx + 1;                 // window start si
    const int coff = (s & 1) * CPY;          // odd start -> shifted copy
    const int bhx  = s & ~1;

    unsigned cp2[PY], ct2[PY];
#pragma unroll
    for (int k = 0; k < PY; k++) {
        int ci = (base + k + 3) * PITCH + tx + 4;   // center si = tx+4
        cp2[k] = (unsigned)sm[ci] * 0x00010001u;
        ct2[k] = (unsigned)sm[2 * CPY + ci] * 0x00010001u;
    }

    unsigned accM = 0, accA = 0;    // SIMD 16-bit field accumulators
#pragma unroll
    for (int r = 0; r < PY + 6; r++) {
        const int rb = (base + r) * PITCH + bhx + coff;
        unsigned vp[4], vt[4];
#pragma unroll
        for (int i = 0; i < 4; i++) {
            vp[i] = *(const unsigned*)&sm[rb + 2 * i];
            vt[i] = *(const unsigned*)&sm[2 * CPY + rb + 2 * i];
        }
#pragma unroll
        for (int k = 0; k < PY; k++) {
            const int dy = r - 3 - k;
            if (dy < -3 || dy > 3) continue;        // compile-time pruned
            unsigned x0m = gt2(cp2[k], vp[0]) ^ gt2(ct2[k], vt[0]);
            unsigned x1m = gt2(cp2[k], vp[1]) ^ gt2(ct2[k], vt[1]);
            unsigned x2m = gt2(cp2[k], vp[2]) ^ gt2(ct2[k], vt[2]);
            unsigned x3m = gt2(cp2[k], vp[3]) ^ gt2(ct2[k], vt[3]);
            accM = __vsub2(accM, x0m);   // 0xFFFF field == -1 -> +1 per mismatch
            accM = __vsub2(accM, x1m);
            accM = __vsub2(accM, x2m);
            accA = __vsub2(accA, x3m);   // hi lane (dx=+4) invalid -> discarded
            // center self-compare (dy==0, dx==0 lane) is 0 automatically
        }
    }
    int cnt = (int)(accM & 0xFFFFu) + (int)(accM >> 16) + (int)(accA & 0xFFFFu);

    // Warp + block reduction
    cnt = __reduce_add_sync(0xffffffffu, cnt);
    if (tx == 0) wsum[threadIdx.y] = cnt;
    __syncthreads();

    if (tid == 0) {
        int v = 0;
#pragma unroll
        for (int w = 0; w < TYW; w++) v += wsum[w];
        unsigned long long old =
            atomicAdd(&g_pack, (unsigned long long)v + (1ULL << 40));
        if ((old >> 40) == NBLOCKS - 1) {
            unsigned long long tot = (old & ((1ULL << 40) - 1)) + (unsigned long long)v;
            const double denom = 48.0 * (double)BB * (double)HW;  // 100663296
            out[0] = (float)((double)tot / denom);
            g_pack = 0ULL;    // reset for next graph replay
        }
    }
}

extern "C" void kernel_launch(void* const* d_in, const int* in_sizes, int n_in,
                              void* d_out, int out_size) {
    const float* pred = (const float*)d_in[0];
    const float* tgt  = (const float*)d_in[1];
    float* out = (float*)d_out;
    (void)in_sizes; (void)n_in; (void)out_size;

    dim3 bdim(TX, TYW);
    dim3 gdim(WW / TX, HH / TILE_H, BB);
    census_fused<<<gdim, bdim>>>(pred, tgt, out);
}